// round 8
// baseline (speedup 1.0000x reference)
#include <cuda_runtime.h>
#include <stdint.h>

#define BB 4
#define NP 8192
#define NG 8192
#define T  256          // threads per block
#define Q  8            // queries per thread
#define SLA 16          // gt slices (acc direction)  -> L ~ cnt/16 (~256)
#define PS 32           // pred slices (com direction)
#define PSL (NP / PS)   // 256 pred points per slice
#define GRID_X (NP / (T * Q))           // 4
#define NTA (GRID_X * SLA * BB)         // 256 acc tasks
#define NTC (GRID_X * PS * BB)          // 512 com tasks
#define NBLK 148                        // 1 CTA/SM, all co-resident at any regcount
#define TILE_MAX 512                    // max points per tile (8 KB smem)

#define INF_BITS 0x7F800000u

// ---------------- device scratch (no allocs; all counters self-reset per replay) ----------------
__device__ float    g_gt[BB][3][NG];   // compacted valid gt, SoA ([cnt,NG) = stale, never used)
__device__ float    g_gtsq[BB][NG];    // |g|^2 per compacted gt
__device__ int      g_gtidx[BB][NG];   // original gt index of compacted entry
__device__ int      g_cnt[BB];         // zero-init (.bss), reset at end of each replay
__device__ unsigned g_prmin[BB * NP];  // per-pred min d2 (float bits)
__device__ unsigned g_gtmin[BB * NG];  // per-ORIGINAL-gt min d2 (float bits)
__device__ int      g_bad;             // 1 => gt_valid is 1-byte bool; 0 => int32
__device__ int      g_bar1, g_bar2;    // grid barrier counters
__device__ int      g_taskA, g_taskC;  // dynamic task counters (acc / com)
__device__ int      g_done;            // completion counter

// ---------------- packed f32x2 helpers ----------------
__device__ __forceinline__ unsigned long long f2pk(float lo, float hi) {
    unsigned long long r;
    asm("mov.b64 %0, {%1,%2};" : "=l"(r) : "f"(lo), "f"(hi));
    return r;
}
__device__ __forceinline__ unsigned long long fma2(unsigned long long a, unsigned long long b,
                                                   unsigned long long c) {
    unsigned long long r;
    asm("fma.rn.f32x2 %0, %1, %2, %3;" : "=l"(r) : "l"(a), "l"(b), "l"(c));
    return r;
}
__device__ __forceinline__ void upk(unsigned long long v, float& lo, float& hi) {
    asm("mov.b64 {%0,%1}, %2;" : "=f"(lo), "=f"(hi) : "l"(v));
}

// Grid barrier: safe because 148 blocks at 1 CTA/SM are all co-resident.
__device__ __forceinline__ void grid_barrier(int* ctr) {
    __syncthreads();
    if (threadIdx.x == 0) {
        __threadfence();                 // release this block's prior writes
        atomicAdd(ctr, 1);
        while (atomicAdd(ctr, 0) < NBLK) __nanosleep(64);
        __threadfence();                 // acquire other blocks' writes
    }
    __syncthreads();
}

// One Chamfer tile-task, specialized per direction (no runtime is_acc in hot loop).
template <bool IS_ACC>
__device__ __forceinline__ void do_task(int task, const float* __restrict__ pr,
                                        float4* s, int tid) {
    int xg = task & (GRID_X - 1);
    int zz = task >> 2;
    int b, slice;
    if (IS_ACC) { b = zz >> 4; slice = zz & (SLA - 1); }
    else        { b = zz >> 5; slice = zz & (PS - 1); }
    int cnt = g_cnt[b];

    int qbase = xg * (T * Q);
    int tileLen, t0;
    if (IS_ACC) {
        int npad = (cnt + 7) & ~7;
        int L = (((npad + SLA - 1) / SLA) + 7) & ~7;   // slice len, mult of 8, <= 512
        t0 = slice * L;
        int t1 = min(t0 + L, npad);
        if (t0 >= t1) return;
        tileLen = t1 - t0;
    } else {
        t0 = slice * PSL;
        tileLen = PSL;
        if (qbase >= cnt) return;
    }

    if (IS_ACC) {
        for (int i = tid; i < tileLen; i += T) {
            int idx = t0 + i;
            float x, y, z, sq;
            if (idx < cnt) {
                x = g_gt[b][0][idx]; y = g_gt[b][1][idx]; z = g_gt[b][2][idx];
                sq = g_gtsq[b][idx];
            } else {  // in-register sentinel (pad region, <= 7 entries)
                x = 0.f; y = 0.f; z = 0.f; sq = __uint_as_float(INF_BITS);
            }
            float* base = reinterpret_cast<float*>(&s[(i >> 1) * 2]);
            int h = i & 1;
            base[0 + h] = x; base[2 + h] = y; base[4 + h] = z; base[6 + h] = sq;
        }
    } else {
        for (int i = tid; i < tileLen; i += T) {
            const float* p = pr + ((size_t)b * NP + t0 + i) * 3;
            float x = p[0], y = p[1], z = p[2];
            float sq = x * x + y * y + z * z;
            float* base = reinterpret_cast<float*>(&s[(i >> 1) * 2]);
            int h = i & 1;
            base[0 + h] = x; base[2 + h] = y; base[4 + h] = z; base[6 + h] = sq;
        }
    }
    __syncthreads();

    unsigned long long q2x[Q], q2y[Q], q2z[Q];
    float qsq[Q], m0[Q], m1[Q];
#pragma unroll
    for (int q = 0; q < Q; q++) {
        int qq = qbase + tid + q * T;
        float x, y, z, sq;
        if (IS_ACC) {
            const float* p = pr + ((size_t)b * NP + qq) * 3;
            x = p[0]; y = p[1]; z = p[2];
            sq = x * x + y * y + z * z;
        } else {
            // qq >= cnt reads stale data; result discarded at the atomic
            x = g_gt[b][0][qq]; y = g_gt[b][1][qq]; z = g_gt[b][2][qq];
            sq = (qq < cnt) ? g_gtsq[b][qq] : 0.f;
        }
        float nx = -2.f * x, ny = -2.f * y, nz = -2.f * z;
        q2x[q] = f2pk(nx, nx); q2y[q] = f2pk(ny, ny); q2z[q] = f2pk(nz, nz);
        qsq[q] = sq;
        m0[q] = __uint_as_float(INF_BITS);
        m1[q] = __uint_as_float(INF_BITS);
    }

    int pairs = tileLen >> 1;
#pragma unroll 2
    for (int k = 0; k < pairs; k++) {
        float4 a  = s[k * 2];
        float4 bv = s[k * 2 + 1];
        unsigned long long gx = f2pk(a.x, a.y);
        unsigned long long gy = f2pk(a.z, a.w);
        unsigned long long gz = f2pk(bv.x, bv.y);
        unsigned long long gs = f2pk(bv.z, bv.w);
#pragma unroll
        for (int q = 0; q < Q; q++) {
            unsigned long long t = fma2(q2x[q], gx, fma2(q2y[q], gy, fma2(q2z[q], gz, gs)));
            float tl, th; upk(t, tl, th);
            m0[q] = fminf(m0[q], tl);
            m1[q] = fminf(m1[q], th);
        }
    }

#pragma unroll
    for (int q = 0; q < Q; q++) {
        int qq = qbase + tid + q * T;
        float m = fmaxf(fminf(m0[q], m1[q]) + qsq[q], 0.f);
        if (IS_ACC) {
            atomicMin(&g_prmin[b * NP + qq], __float_as_uint(m));
        } else if (qq < cnt) {
            int orig = g_gtidx[b][qq];
            atomicMin(&g_gtmin[b * NG + orig], __float_as_uint(m));
        }
    }
}

// ---------------- the single persistent kernel ----------------
__global__ void __launch_bounds__(T) k_all(const float* __restrict__ pr,
                                           const float* __restrict__ gt,
                                           const void* __restrict__ valid,
                                           float* __restrict__ out) {
    int tid = threadIdx.x;
    int gtid = blockIdx.x * T + tid;
    int gstride = NBLK * T;   // 37888 threads

    // ======== Phase A: reset min arrays + detect gt_valid format ========
    for (int k = gtid; k < BB * NP; k += gstride) g_prmin[k] = INF_BITS;
    for (int k = gtid; k < BB * NG; k += gstride) g_gtmin[k] = INF_BITS;
    {
        // read only (BB*NG)/4 = 8192 words: safe under both layouts.
        // byte-bool packs 4 flags/word -> some word > 1; int32 words are all 0/1.
        const unsigned* w = (const unsigned*)valid;
        int found = 0;
        for (int k = gtid; k < (BB * NG) / 4; k += gstride)
            if (w[k] > 1u) found = 1;
        if (found) g_bad = 1;
    }
    grid_barrier(&g_bar1);

    // ======== Phase B: warp-aggregated compaction (first BB*NG threads) ========
    if (gtid < BB * NG) {
        int fmt_byte = g_bad;   // 1 => byte-bool
        int b = gtid >> 13;     // / NG
        int g = gtid & (NG - 1);
        bool v;
        if (fmt_byte)
            v = (reinterpret_cast<const unsigned char*>(valid)[gtid] != 0);
        else
            v = (reinterpret_cast<const int*>(valid)[gtid] != 0);

        unsigned mask = __ballot_sync(0xffffffffu, v);
        int lane = tid & 31;
        int base = 0;
        if (lane == 0 && mask) base = atomicAdd(&g_cnt[b], __popc(mask));
        base = __shfl_sync(0xffffffffu, base, 0);
        if (v) {
            int p = base + __popc(mask & ((1u << lane) - 1u));
            const float* sgt = gt + (size_t)gtid * 3;
            float x = sgt[0], y = sgt[1], z = sgt[2];
            g_gt[b][0][p] = x;
            g_gt[b][1][p] = y;
            g_gt[b][2][p] = z;
            g_gtsq[b][p]  = x * x + y * y + z * z;
            g_gtidx[b][p] = g;
        }
    }
    grid_barrier(&g_bar2);

    // ======== Phase C: dynamic task loops (acc first, then com) ========
    __shared__ __align__(16) float4 s[TILE_MAX];  // 8 KB
    __shared__ int s_task;

    while (true) {
        if (tid == 0) s_task = atomicAdd(&g_taskA, 1);
        __syncthreads();
        int task = s_task;
        if (task >= NTA) break;
        do_task<true>(task, pr, s, tid);
        __syncthreads();   // protect smem tile + s_task reuse
    }
    while (true) {
        if (tid == 0) s_task = atomicAdd(&g_taskC, 1);
        __syncthreads();
        int task = s_task;
        if (task >= NTC) break;
        do_task<false>(task, pr, s, tid);
        __syncthreads();
    }

    // ======== Phase D: last block reduces + resets all counters ========
    __shared__ bool isLast;
    __shared__ float sa;
    __shared__ float sc[BB];
    __threadfence();
    __syncthreads();
    if (tid == 0) {
        int prev = atomicAdd(&g_done, 1);
        isLast = (prev == NBLK - 1);
        if (isLast) __threadfence();   // acquire all blocks' writes
        sa = 0.f;
    }
    if (tid < BB) sc[tid] = 0.f;
    __syncthreads();
    if (!isLast) return;

    float la = 0.f;
    for (int i = tid; i < BB * NP; i += T)
        la += __uint_as_float(g_prmin[i]);
    atomicAdd(&sa, la);

    for (int bb = 0; bb < BB; bb++) {
        float lc = 0.f;
        for (int i = tid; i < NG; i += T) {
            unsigned v = g_gtmin[bb * NG + i];
            if (v != INF_BITS) lc += __uint_as_float(v);  // only valid gt were written
        }
        atomicAdd(&sc[bb], lc);
    }
    __syncthreads();

    if (tid == 0) {
        float loss_acc = sa / (float)(BB * NP);
        float loss_com = 0.f;
        for (int bb = 0; bb < BB; bb++)
            loss_com += sc[bb] / fmaxf((float)g_cnt[bb], 1.f);
        loss_com /= (float)BB;
        out[0] = 2.f * (loss_acc + loss_com);  // acc + com + cd, cd = acc + com

        // reset ALL mutable state for the next graph replay
        for (int bb = 0; bb < BB; bb++) g_cnt[bb] = 0;
        g_bad = 0; g_bar1 = 0; g_bar2 = 0; g_taskA = 0; g_taskC = 0; g_done = 0;
    }
}

// ---------------- launch ----------------
extern "C" void kernel_launch(void* const* d_in, const int* in_sizes, int n_in,
                              void* d_out, int out_size) {
    const float* pr    = (const float*)d_in[0];  // [B,NP,3] f32
    const float* gt    = (const float*)d_in[1];  // [B,NG,3] f32
    const void*  valid = d_in[2];                // [B,NG] bool(1B) or int32

    k_all<<<NBLK, T>>>(pr, gt, valid, (float*)d_out);
}

// round 9
// speedup vs baseline: 1.0785x; 1.0785x over previous
#include <cuda_runtime.h>
#include <stdint.h>

#define BB 4
#define NP 8192
#define NG 8192
#define T  256          // threads per block
#define Q  8            // queries per thread
#define SLA 16          // gt slices (acc direction)  -> L ~ cnt/16 (~256)
#define PS 32           // pred slices (com direction)
#define PSL (NP / PS)   // 256 pred points per slice
#define GRID_X (NP / (T * Q))           // 4
#define NTA (GRID_X * SLA * BB)         // 256 acc tasks
#define NTC (GRID_X * PS * BB)          // 512 com tasks
#define NBLK 296                        // 2 CTAs/SM x 148 SMs, co-resident (regs capped 128, need ~72)
#define TILE_MAX 512                    // max points per tile (8 KB smem)

#define INF_BITS 0x7F800000u

// ---------------- device scratch (no allocs; all counters self-reset per replay) ----------------
__device__ float    g_gt[BB][3][NG];   // compacted valid gt, SoA ([cnt,NG) = stale, never used)
__device__ float    g_gtsq[BB][NG];    // |g|^2 per compacted gt
__device__ int      g_gtidx[BB][NG];   // original gt index of compacted entry
__device__ int      g_cnt[BB];         // zero-init (.bss), reset at end of each replay
__device__ unsigned g_prmin[BB * NP];  // per-pred min d2 (float bits)
__device__ unsigned g_gtmin[BB * NG];  // per-ORIGINAL-gt min d2 (float bits)
__device__ int      g_bad;             // 1 => gt_valid is 1-byte bool; 0 => int32
__device__ int      g_bar1, g_bar2;    // grid barrier counters
__device__ int      g_taskA, g_taskC;  // dynamic task counters (acc / com)
__device__ int      g_done;            // completion counter

// ---------------- packed f32x2 helpers ----------------
__device__ __forceinline__ unsigned long long f2pk(float lo, float hi) {
    unsigned long long r;
    asm("mov.b64 %0, {%1,%2};" : "=l"(r) : "f"(lo), "f"(hi));
    return r;
}
__device__ __forceinline__ unsigned long long fma2(unsigned long long a, unsigned long long b,
                                                   unsigned long long c) {
    unsigned long long r;
    asm("fma.rn.f32x2 %0, %1, %2, %3;" : "=l"(r) : "l"(a), "l"(b), "l"(c));
    return r;
}
__device__ __forceinline__ void upk(unsigned long long v, float& lo, float& hi) {
    asm("mov.b64 {%0,%1}, %2;" : "=f"(lo), "=f"(hi) : "l"(v));
}

// Grid barrier: safe because all NBLK blocks are co-resident
// (__launch_bounds__(T,2) guarantees 2 CTAs/SM fit: regs<=128, smem ~8KB).
__device__ __forceinline__ void grid_barrier(int* ctr) {
    __syncthreads();
    if (threadIdx.x == 0) {
        __threadfence();                 // release this block's prior writes
        atomicAdd(ctr, 1);
        while (atomicAdd(ctr, 0) < NBLK) __nanosleep(64);
        __threadfence();                 // acquire other blocks' writes
    }
    __syncthreads();
}

// One Chamfer tile-task, specialized per direction (no runtime is_acc in hot loop).
template <bool IS_ACC>
__device__ __forceinline__ void do_task(int task, const float* __restrict__ pr,
                                        float4* s, int tid) {
    int xg = task & (GRID_X - 1);
    int zz = task >> 2;
    int b, slice;
    if (IS_ACC) { b = zz >> 4; slice = zz & (SLA - 1); }
    else        { b = zz >> 5; slice = zz & (PS - 1); }
    int cnt = g_cnt[b];

    int qbase = xg * (T * Q);
    int tileLen, t0;
    if (IS_ACC) {
        int npad = (cnt + 7) & ~7;
        int L = (((npad + SLA - 1) / SLA) + 7) & ~7;   // slice len, mult of 8, <= 512
        t0 = slice * L;
        int t1 = min(t0 + L, npad);
        if (t0 >= t1) return;
        tileLen = t1 - t0;
    } else {
        t0 = slice * PSL;
        tileLen = PSL;
        if (qbase >= cnt) return;
    }

    if (IS_ACC) {
        for (int i = tid; i < tileLen; i += T) {
            int idx = t0 + i;
            float x, y, z, sq;
            if (idx < cnt) {
                x = g_gt[b][0][idx]; y = g_gt[b][1][idx]; z = g_gt[b][2][idx];
                sq = g_gtsq[b][idx];
            } else {  // in-register sentinel (pad region, <= 7 entries)
                x = 0.f; y = 0.f; z = 0.f; sq = __uint_as_float(INF_BITS);
            }
            float* base = reinterpret_cast<float*>(&s[(i >> 1) * 2]);
            int h = i & 1;
            base[0 + h] = x; base[2 + h] = y; base[4 + h] = z; base[6 + h] = sq;
        }
    } else {
        for (int i = tid; i < tileLen; i += T) {
            const float* p = pr + ((size_t)b * NP + t0 + i) * 3;
            float x = p[0], y = p[1], z = p[2];
            float sq = x * x + y * y + z * z;
            float* base = reinterpret_cast<float*>(&s[(i >> 1) * 2]);
            int h = i & 1;
            base[0 + h] = x; base[2 + h] = y; base[4 + h] = z; base[6 + h] = sq;
        }
    }
    __syncthreads();

    unsigned long long q2x[Q], q2y[Q], q2z[Q];
    float qsq[Q], m0[Q], m1[Q];
#pragma unroll
    for (int q = 0; q < Q; q++) {
        int qq = qbase + tid + q * T;
        float x, y, z, sq;
        if (IS_ACC) {
            const float* p = pr + ((size_t)b * NP + qq) * 3;
            x = p[0]; y = p[1]; z = p[2];
            sq = x * x + y * y + z * z;
        } else {
            // qq >= cnt reads stale data; result discarded at the atomic
            x = g_gt[b][0][qq]; y = g_gt[b][1][qq]; z = g_gt[b][2][qq];
            sq = (qq < cnt) ? g_gtsq[b][qq] : 0.f;
        }
        float nx = -2.f * x, ny = -2.f * y, nz = -2.f * z;
        q2x[q] = f2pk(nx, nx); q2y[q] = f2pk(ny, ny); q2z[q] = f2pk(nz, nz);
        qsq[q] = sq;
        m0[q] = __uint_as_float(INF_BITS);
        m1[q] = __uint_as_float(INF_BITS);
    }

    int pairs = tileLen >> 1;
#pragma unroll 2
    for (int k = 0; k < pairs; k++) {
        float4 a  = s[k * 2];
        float4 bv = s[k * 2 + 1];
        unsigned long long gx = f2pk(a.x, a.y);
        unsigned long long gy = f2pk(a.z, a.w);
        unsigned long long gz = f2pk(bv.x, bv.y);
        unsigned long long gs = f2pk(bv.z, bv.w);
#pragma unroll
        for (int q = 0; q < Q; q++) {
            unsigned long long t = fma2(q2x[q], gx, fma2(q2y[q], gy, fma2(q2z[q], gz, gs)));
            float tl, th; upk(t, tl, th);
            m0[q] = fminf(m0[q], tl);
            m1[q] = fminf(m1[q], th);
        }
    }

#pragma unroll
    for (int q = 0; q < Q; q++) {
        int qq = qbase + tid + q * T;
        float m = fmaxf(fminf(m0[q], m1[q]) + qsq[q], 0.f);
        if (IS_ACC) {
            atomicMin(&g_prmin[b * NP + qq], __float_as_uint(m));
        } else if (qq < cnt) {
            int orig = g_gtidx[b][qq];
            atomicMin(&g_gtmin[b * NG + orig], __float_as_uint(m));
        }
    }
}

// ---------------- the single persistent kernel ----------------
__global__ void __launch_bounds__(T, 2) k_all(const float* __restrict__ pr,
                                              const float* __restrict__ gt,
                                              const void* __restrict__ valid,
                                              float* __restrict__ out) {
    int tid = threadIdx.x;
    int gtid = blockIdx.x * T + tid;
    int gstride = NBLK * T;   // 75776 threads

    // ======== Phase A: reset min arrays + detect gt_valid format ========
    for (int k = gtid; k < BB * NP; k += gstride) g_prmin[k] = INF_BITS;
    for (int k = gtid; k < BB * NG; k += gstride) g_gtmin[k] = INF_BITS;
    {
        // read only (BB*NG)/4 = 8192 words: safe under both layouts.
        // byte-bool packs 4 flags/word -> some word > 1; int32 words are all 0/1.
        const unsigned* w = (const unsigned*)valid;
        int found = 0;
        for (int k = gtid; k < (BB * NG) / 4; k += gstride)
            if (w[k] > 1u) found = 1;
        if (found) g_bad = 1;
    }
    grid_barrier(&g_bar1);

    // ======== Phase B: warp-aggregated compaction (first BB*NG threads) ========
    if (gtid < BB * NG) {
        int fmt_byte = g_bad;   // 1 => byte-bool
        int b = gtid >> 13;     // / NG
        int g = gtid & (NG - 1);
        bool v;
        if (fmt_byte)
            v = (reinterpret_cast<const unsigned char*>(valid)[gtid] != 0);
        else
            v = (reinterpret_cast<const int*>(valid)[gtid] != 0);

        unsigned mask = __ballot_sync(0xffffffffu, v);
        int lane = tid & 31;
        int base = 0;
        if (lane == 0 && mask) base = atomicAdd(&g_cnt[b], __popc(mask));
        base = __shfl_sync(0xffffffffu, base, 0);
        if (v) {
            int p = base + __popc(mask & ((1u << lane) - 1u));
            const float* sgt = gt + (size_t)gtid * 3;
            float x = sgt[0], y = sgt[1], z = sgt[2];
            g_gt[b][0][p] = x;
            g_gt[b][1][p] = y;
            g_gt[b][2][p] = z;
            g_gtsq[b][p]  = x * x + y * y + z * z;
            g_gtidx[b][p] = g;
        }
    }
    grid_barrier(&g_bar2);

    // ======== Phase C: dynamic task loops (acc first, then com) ========
    __shared__ __align__(16) float4 s[TILE_MAX];  // 8 KB
    __shared__ int s_task;

    while (true) {
        if (tid == 0) s_task = atomicAdd(&g_taskA, 1);
        __syncthreads();
        int task = s_task;
        if (task >= NTA) break;
        do_task<true>(task, pr, s, tid);
        __syncthreads();   // protect smem tile + s_task reuse
    }
    while (true) {
        if (tid == 0) s_task = atomicAdd(&g_taskC, 1);
        __syncthreads();
        int task = s_task;
        if (task >= NTC) break;
        do_task<false>(task, pr, s, tid);
        __syncthreads();
    }

    // ======== Phase D: last block reduces + resets all counters ========
    __shared__ bool isLast;
    __shared__ float sa;
    __shared__ float sc[BB];
    __threadfence();
    __syncthreads();
    if (tid == 0) {
        int prev = atomicAdd(&g_done, 1);
        isLast = (prev == NBLK - 1);
        if (isLast) __threadfence();   // acquire all blocks' writes
        sa = 0.f;
    }
    if (tid < BB) sc[tid] = 0.f;
    __syncthreads();
    if (!isLast) return;

    float la = 0.f;
    for (int i = tid; i < BB * NP; i += T)
        la += __uint_as_float(g_prmin[i]);
    atomicAdd(&sa, la);

    for (int bb = 0; bb < BB; bb++) {
        float lc = 0.f;
        for (int i = tid; i < NG; i += T) {
            unsigned v = g_gtmin[bb * NG + i];
            if (v != INF_BITS) lc += __uint_as_float(v);  // only valid gt were written
        }
        atomicAdd(&sc[bb], lc);
    }
    __syncthreads();

    if (tid == 0) {
        float loss_acc = sa / (float)(BB * NP);
        float loss_com = 0.f;
        for (int bb = 0; bb < BB; bb++)
            loss_com += sc[bb] / fmaxf((float)g_cnt[bb], 1.f);
        loss_com /= (float)BB;
        out[0] = 2.f * (loss_acc + loss_com);  // acc + com + cd, cd = acc + com

        // reset ALL mutable state for the next graph replay
        for (int bb = 0; bb < BB; bb++) g_cnt[bb] = 0;
        g_bad = 0; g_bar1 = 0; g_bar2 = 0; g_taskA = 0; g_taskC = 0; g_done = 0;
    }
}

// ---------------- launch ----------------
extern "C" void kernel_launch(void* const* d_in, const int* in_sizes, int n_in,
                              void* d_out, int out_size) {
    const float* pr    = (const float*)d_in[0];  // [B,NP,3] f32
    const float* gt    = (const float*)d_in[1];  // [B,NG,3] f32
    const void*  valid = d_in[2];                // [B,NG] bool(1B) or int32

    k_all<<<NBLK, T>>>(pr, gt, valid, (float*)d_out);
}

// round 10
// speedup vs baseline: 1.1868x; 1.1004x over previous
#include <cuda_runtime.h>
#include <stdint.h>

#define BB 4
#define NP 8192
#define NG 8192
#define T  128          // threads per block
#define Q  8            // queries per thread
#define SLA 16          // gt slices (acc direction)  -> L ~ cnt/16 (~256)
#define PS 32           // pred slices (com direction)
#define PSL (NP / PS)   // 256 pred points per slice
#define GRID_X (NP / (T * Q))           // 8
#define NTA (GRID_X * SLA * BB)         // 512 acc tasks
#define NTC (GRID_X * PS * BB)          // 1024 com tasks
#define NBLK 740                        // 5 CTAs/SM x 148 SMs, all co-resident
#define TILE_MAX 512                    // max points per tile (8 KB smem)

#define INF_BITS 0x7F800000u

// ---------------- device scratch (no allocs; all counters self-reset per replay) ----------------
__device__ float    g_gt[BB][3][NG];   // compacted valid gt, SoA ([cnt,NG) = stale, never used)
__device__ float    g_gtsq[BB][NG];    // |g|^2 per compacted gt
__device__ int      g_gtidx[BB][NG];   // original gt index of compacted entry
__device__ int      g_cnt[BB];         // zero-init (.bss), reset at end of each replay
__device__ unsigned g_prmin[BB * NP];  // per-pred min d2 (float bits)
__device__ unsigned g_gtmin[BB * NG];  // per-ORIGINAL-gt min d2 (float bits)
__device__ int      g_bad;             // 1 => gt_valid is 1-byte bool; 0 => int32
__device__ int      g_bar1, g_bar2;    // grid barrier counters
__device__ int      g_taskA, g_taskC;  // dynamic task counters (acc / com)
__device__ int      g_done;            // completion counter

// ---------------- packed f32x2 helpers ----------------
__device__ __forceinline__ unsigned long long f2pk(float lo, float hi) {
    unsigned long long r;
    asm("mov.b64 %0, {%1,%2};" : "=l"(r) : "f"(lo), "f"(hi));
    return r;
}
__device__ __forceinline__ unsigned long long fma2(unsigned long long a, unsigned long long b,
                                                   unsigned long long c) {
    unsigned long long r;
    asm("fma.rn.f32x2 %0, %1, %2, %3;" : "=l"(r) : "l"(a), "l"(b), "l"(c));
    return r;
}
__device__ __forceinline__ void upk(unsigned long long v, float& lo, float& hi) {
    asm("mov.b64 {%0,%1}, %2;" : "=f"(lo), "=f"(hi) : "l"(v));
}

// Grid barrier: safe because all NBLK blocks are co-resident
// (__launch_bounds__(T,5): regs<=102 (need ~98), smem 5x8.2KB = 41KB).
__device__ __forceinline__ void grid_barrier(int* ctr) {
    __syncthreads();
    if (threadIdx.x == 0) {
        __threadfence();                 // release this block's prior writes
        atomicAdd(ctr, 1);
        while (atomicAdd(ctr, 0) < NBLK) __nanosleep(64);
        __threadfence();                 // acquire other blocks' writes
    }
    __syncthreads();
}

// One Chamfer tile-task, specialized per direction (no runtime is_acc in hot loop).
template <bool IS_ACC>
__device__ __forceinline__ void do_task(int task, const float* __restrict__ pr,
                                        float4* s, int tid) {
    int xg = task & (GRID_X - 1);
    int zz = task >> 3;                 // GRID_X = 8
    int b, slice;
    if (IS_ACC) { b = zz >> 4; slice = zz & (SLA - 1); }
    else        { b = zz >> 5; slice = zz & (PS - 1); }
    int cnt = g_cnt[b];

    int qbase = xg * (T * Q);
    int tileLen, t0;
    if (IS_ACC) {
        int npad = (cnt + 7) & ~7;
        int L = (((npad + SLA - 1) / SLA) + 7) & ~7;   // slice len, mult of 8, <= 512
        t0 = slice * L;
        int t1 = min(t0 + L, npad);
        if (t0 >= t1) return;
        tileLen = t1 - t0;
    } else {
        t0 = slice * PSL;
        tileLen = PSL;
        if (qbase >= cnt) return;
    }

    if (IS_ACC) {
        for (int i = tid; i < tileLen; i += T) {
            int idx = t0 + i;
            float x, y, z, sq;
            if (idx < cnt) {
                x = g_gt[b][0][idx]; y = g_gt[b][1][idx]; z = g_gt[b][2][idx];
                sq = g_gtsq[b][idx];
            } else {  // in-register sentinel (pad region, <= 7 entries)
                x = 0.f; y = 0.f; z = 0.f; sq = __uint_as_float(INF_BITS);
            }
            float* base = reinterpret_cast<float*>(&s[(i >> 1) * 2]);
            int h = i & 1;
            base[0 + h] = x; base[2 + h] = y; base[4 + h] = z; base[6 + h] = sq;
        }
    } else {
        for (int i = tid; i < tileLen; i += T) {
            const float* p = pr + ((size_t)b * NP + t0 + i) * 3;
            float x = p[0], y = p[1], z = p[2];
            float sq = x * x + y * y + z * z;
            float* base = reinterpret_cast<float*>(&s[(i >> 1) * 2]);
            int h = i & 1;
            base[0 + h] = x; base[2 + h] = y; base[4 + h] = z; base[6 + h] = sq;
        }
    }
    __syncthreads();

    unsigned long long q2x[Q], q2y[Q], q2z[Q];
    float qsq[Q], m0[Q], m1[Q];
#pragma unroll
    for (int q = 0; q < Q; q++) {
        int qq = qbase + tid + q * T;
        float x, y, z, sq;
        if (IS_ACC) {
            const float* p = pr + ((size_t)b * NP + qq) * 3;
            x = p[0]; y = p[1]; z = p[2];
            sq = x * x + y * y + z * z;
        } else {
            // qq >= cnt reads stale data; result discarded at the atomic
            x = g_gt[b][0][qq]; y = g_gt[b][1][qq]; z = g_gt[b][2][qq];
            sq = (qq < cnt) ? g_gtsq[b][qq] : 0.f;
        }
        float nx = -2.f * x, ny = -2.f * y, nz = -2.f * z;
        q2x[q] = f2pk(nx, nx); q2y[q] = f2pk(ny, ny); q2z[q] = f2pk(nz, nz);
        qsq[q] = sq;
        m0[q] = __uint_as_float(INF_BITS);
        m1[q] = __uint_as_float(INF_BITS);
    }

    int pairs = tileLen >> 1;
#pragma unroll 2
    for (int k = 0; k < pairs; k++) {
        float4 a  = s[k * 2];
        float4 bv = s[k * 2 + 1];
        unsigned long long gx = f2pk(a.x, a.y);
        unsigned long long gy = f2pk(a.z, a.w);
        unsigned long long gz = f2pk(bv.x, bv.y);
        unsigned long long gs = f2pk(bv.z, bv.w);
#pragma unroll
        for (int q = 0; q < Q; q++) {
            unsigned long long t = fma2(q2x[q], gx, fma2(q2y[q], gy, fma2(q2z[q], gz, gs)));
            float tl, th; upk(t, tl, th);
            m0[q] = fminf(m0[q], tl);
            m1[q] = fminf(m1[q], th);
        }
    }

#pragma unroll
    for (int q = 0; q < Q; q++) {
        int qq = qbase + tid + q * T;
        float m = fmaxf(fminf(m0[q], m1[q]) + qsq[q], 0.f);
        if (IS_ACC) {
            atomicMin(&g_prmin[b * NP + qq], __float_as_uint(m));
        } else if (qq < cnt) {
            int orig = g_gtidx[b][qq];
            atomicMin(&g_gtmin[b * NG + orig], __float_as_uint(m));
        }
    }
}

// ---------------- the single persistent kernel ----------------
__global__ void __launch_bounds__(T, 5) k_all(const float* __restrict__ pr,
                                              const float* __restrict__ gt,
                                              const void* __restrict__ valid,
                                              float* __restrict__ out) {
    int tid = threadIdx.x;
    int gtid = blockIdx.x * T + tid;
    int gstride = NBLK * T;   // 94720 threads

    // ======== Phase A: reset min arrays + detect gt_valid format ========
    for (int k = gtid; k < BB * NP; k += gstride) g_prmin[k] = INF_BITS;
    for (int k = gtid; k < BB * NG; k += gstride) g_gtmin[k] = INF_BITS;
    {
        // read only (BB*NG)/4 = 8192 words: safe under both layouts.
        // byte-bool packs 4 flags/word -> some word > 1; int32 words are all 0/1.
        const unsigned* w = (const unsigned*)valid;
        int found = 0;
        for (int k = gtid; k < (BB * NG) / 4; k += gstride)
            if (w[k] > 1u) found = 1;
        if (found) g_bad = 1;
    }
    grid_barrier(&g_bar1);

    // ======== Phase B: warp-aggregated compaction (first BB*NG threads) ========
    if (gtid < BB * NG) {
        int fmt_byte = g_bad;   // 1 => byte-bool
        int b = gtid >> 13;     // / NG
        int g = gtid & (NG - 1);
        bool v;
        if (fmt_byte)
            v = (reinterpret_cast<const unsigned char*>(valid)[gtid] != 0);
        else
            v = (reinterpret_cast<const int*>(valid)[gtid] != 0);

        unsigned mask = __ballot_sync(0xffffffffu, v);
        int lane = tid & 31;
        int base = 0;
        if (lane == 0 && mask) base = atomicAdd(&g_cnt[b], __popc(mask));
        base = __shfl_sync(0xffffffffu, base, 0);
        if (v) {
            int p = base + __popc(mask & ((1u << lane) - 1u));
            const float* sgt = gt + (size_t)gtid * 3;
            float x = sgt[0], y = sgt[1], z = sgt[2];
            g_gt[b][0][p] = x;
            g_gt[b][1][p] = y;
            g_gt[b][2][p] = z;
            g_gtsq[b][p]  = x * x + y * y + z * z;
            g_gtidx[b][p] = g;
        }
    }
    grid_barrier(&g_bar2);

    // ======== Phase C: dynamic task loops (acc first, then com) ========
    __shared__ __align__(16) float4 s[TILE_MAX];  // 8 KB
    __shared__ int s_task;

    while (true) {
        if (tid == 0) s_task = atomicAdd(&g_taskA, 1);
        __syncthreads();
        int task = s_task;
        if (task >= NTA) break;
        do_task<true>(task, pr, s, tid);
        __syncthreads();   // protect smem tile + s_task reuse
    }
    while (true) {
        if (tid == 0) s_task = atomicAdd(&g_taskC, 1);
        __syncthreads();
        int task = s_task;
        if (task >= NTC) break;
        do_task<false>(task, pr, s, tid);
        __syncthreads();
    }

    // ======== Phase D: last block reduces + resets all counters ========
    __shared__ bool isLast;
    __shared__ float sa;
    __shared__ float sc[BB];
    __threadfence();
    __syncthreads();
    if (tid == 0) {
        int prev = atomicAdd(&g_done, 1);
        isLast = (prev == NBLK - 1);
        if (isLast) __threadfence();   // acquire all blocks' writes
        sa = 0.f;
    }
    if (tid < BB) sc[tid] = 0.f;
    __syncthreads();
    if (!isLast) return;

    float la = 0.f;
    for (int i = tid; i < BB * NP; i += T)
        la += __uint_as_float(g_prmin[i]);
    atomicAdd(&sa, la);

    for (int bb = 0; bb < BB; bb++) {
        float lc = 0.f;
        for (int i = tid; i < NG; i += T) {
            unsigned v = g_gtmin[bb * NG + i];
            if (v != INF_BITS) lc += __uint_as_float(v);  // only valid gt were written
        }
        atomicAdd(&sc[bb], lc);
    }
    __syncthreads();

    if (tid == 0) {
        float loss_acc = sa / (float)(BB * NP);
        float loss_com = 0.f;
        for (int bb = 0; bb < BB; bb++)
            loss_com += sc[bb] / fmaxf((float)g_cnt[bb], 1.f);
        loss_com /= (float)BB;
        out[0] = 2.f * (loss_acc + loss_com);  // acc + com + cd, cd = acc + com

        // reset ALL mutable state for the next graph replay
        for (int bb = 0; bb < BB; bb++) g_cnt[bb] = 0;
        g_bad = 0; g_bar1 = 0; g_bar2 = 0; g_taskA = 0; g_taskC = 0; g_done = 0;
    }
}

// ---------------- launch ----------------
extern "C" void kernel_launch(void* const* d_in, const int* in_sizes, int n_in,
                              void* d_out, int out_size) {
    const float* pr    = (const float*)d_in[0];  // [B,NP,3] f32
    const float* gt    = (const float*)d_in[1];  // [B,NG,3] f32
    const void*  valid = d_in[2];                // [B,NG] bool(1B) or int32

    k_all<<<NBLK, T>>>(pr, gt, valid, (float*)d_out);
}